// round 5
// baseline (speedup 1.0000x reference)
#include <cuda_runtime.h>

// Fused kernel: every thread rebuilds the 3x4 SE3 matrix from the 7 scalar
// inputs (uniform broadcast loads, ~100 ALU/MUFU ops — negligible vs HBM),
// then streams 2 float4 columns: y[r] = sum_c M[r][c] * x[c], y[3] = x[3].
__global__ __launch_bounds__(256)
void se3_fused_vec4x2(const float4* __restrict__ x, float4* __restrict__ y,
                      const float* __restrict__ w, const float* __restrict__ v,
                      const float* __restrict__ theta_p, int n4) {
    // ---- matrix build (uniform across all threads) ----
    const float wx = __ldg(w + 0), wy = __ldg(w + 1), wz = __ldg(w + 2);
    const float vx = __ldg(v + 0), vy = __ldg(v + 1), vz = __ldg(v + 2);
    const float theta = __ldg(theta_p);
    const float s = sinf(theta);
    const float c = cosf(theta);
    const float omc = 1.0f - c;     // 1 - cos
    const float tms = theta - s;    // theta - sin

    // K = skew(w); KK = K @ K
    const float K[9]  = { 0.0f, -wz,   wy,
                          wz,    0.0f, -wx,
                         -wy,    wx,   0.0f };
    float KK[9];
    #pragma unroll
    for (int r = 0; r < 3; r++)
        #pragma unroll
        for (int col = 0; col < 3; col++) {
            float acc = 0.0f;
            #pragma unroll
            for (int k = 0; k < 3; k++) acc += K[r * 3 + k] * K[k * 3 + col];
            KK[r * 3 + col] = acc;
        }

    float M[12];  // rows 0..2 of the 4x4; row 3 is [0,0,0,1]
    #pragma unroll
    for (int r = 0; r < 3; r++) {
        float Vr[3];
        #pragma unroll
        for (int col = 0; col < 3; col++) {
            const float I = (r == col) ? 1.0f : 0.0f;
            M[r * 4 + col] = I + s * K[r * 3 + col] + omc * KK[r * 3 + col];
            Vr[col]        = I * theta + omc * K[r * 3 + col] + tms * KK[r * 3 + col];
        }
        M[r * 4 + 3] = Vr[0] * vx + Vr[1] * vy + Vr[2] * vz;
    }
    const float m00 = M[0], m01 = M[1], m02 = M[2],  m03 = M[3];
    const float m10 = M[4], m11 = M[5], m12 = M[6],  m13 = M[7];
    const float m20 = M[8], m21 = M[9], m22 = M[10], m23 = M[11];

    // ---- streaming transform: 2 float4 columns per thread ----
    const size_t base = (size_t)(blockIdx.x * blockDim.x + threadIdx.x) * 2;
    const size_t stride = (size_t)n4;

    #pragma unroll
    for (int u = 0; u < 2; u++) {
        const size_t i = base + u;
        if (i >= stride) return;

        const float4 x0 = __ldcs(x + 0 * stride + i);
        const float4 x1 = __ldcs(x + 1 * stride + i);
        const float4 x2 = __ldcs(x + 2 * stride + i);
        const float4 x3 = __ldcs(x + 3 * stride + i);

        float4 y0, y1, y2;
        y0.x = m00 * x0.x + m01 * x1.x + m02 * x2.x + m03 * x3.x;
        y0.y = m00 * x0.y + m01 * x1.y + m02 * x2.y + m03 * x3.y;
        y0.z = m00 * x0.z + m01 * x1.z + m02 * x2.z + m03 * x3.z;
        y0.w = m00 * x0.w + m01 * x1.w + m02 * x2.w + m03 * x3.w;

        y1.x = m10 * x0.x + m11 * x1.x + m12 * x2.x + m13 * x3.x;
        y1.y = m10 * x0.y + m11 * x1.y + m12 * x2.y + m13 * x3.y;
        y1.z = m10 * x0.z + m11 * x1.z + m12 * x2.z + m13 * x3.z;
        y1.w = m10 * x0.w + m11 * x1.w + m12 * x2.w + m13 * x3.w;

        y2.x = m20 * x0.x + m21 * x1.x + m22 * x2.x + m23 * x3.x;
        y2.y = m20 * x0.y + m21 * x1.y + m22 * x2.y + m23 * x3.y;
        y2.z = m20 * x0.z + m21 * x1.z + m22 * x2.z + m23 * x3.z;
        y2.w = m20 * x0.w + m21 * x1.w + m22 * x2.w + m23 * x3.w;

        __stcs(y + 0 * stride + i, y0);
        __stcs(y + 1 * stride + i, y1);
        __stcs(y + 2 * stride + i, y2);
        __stcs(y + 3 * stride + i, x3);   // bottom row [0,0,0,1]
    }
}

// Scalar tail for N not divisible by 4 (defensive; N=16M is divisible).
__global__ void se3_tail(const float* __restrict__ x, float* __restrict__ y,
                         const float* __restrict__ w, const float* __restrict__ v,
                         const float* __restrict__ theta_p, int N, int start) {
    const int i = start + blockIdx.x * blockDim.x + threadIdx.x;
    if (i >= N) return;

    const float wx = w[0], wy = w[1], wz = w[2];
    const float theta = theta_p[0];
    const float s = sinf(theta), c = cosf(theta);
    const float omc = 1.0f - c, tms = theta - s;
    const float K[9]  = { 0.0f, -wz, wy,  wz, 0.0f, -wx,  -wy, wx, 0.0f };
    float KK[9];
    for (int r = 0; r < 3; r++)
        for (int col = 0; col < 3; col++) {
            float acc = 0.0f;
            for (int k = 0; k < 3; k++) acc += K[r * 3 + k] * K[k * 3 + col];
            KK[r * 3 + col] = acc;
        }
    float M[12];
    for (int r = 0; r < 3; r++) {
        float Vr[3];
        for (int col = 0; col < 3; col++) {
            const float I = (r == col) ? 1.0f : 0.0f;
            M[r * 4 + col] = I + s * K[r * 3 + col] + omc * KK[r * 3 + col];
            Vr[col]        = I * theta + omc * K[r * 3 + col] + tms * KK[r * 3 + col];
        }
        M[r * 4 + 3] = Vr[0] * v[0] + Vr[1] * v[1] + Vr[2] * v[2];
    }

    const float a = x[0 * (size_t)N + i];
    const float b = x[1 * (size_t)N + i];
    const float cc = x[2 * (size_t)N + i];
    const float d = x[3 * (size_t)N + i];
    y[0 * (size_t)N + i] = M[0] * a + M[1] * b + M[2]  * cc + M[3]  * d;
    y[1 * (size_t)N + i] = M[4] * a + M[5] * b + M[6]  * cc + M[7]  * d;
    y[2 * (size_t)N + i] = M[8] * a + M[9] * b + M[10] * cc + M[11] * d;
    y[3 * (size_t)N + i] = d;
}

extern "C" void kernel_launch(void* const* d_in, const int* in_sizes, int n_in,
                              void* d_out, int out_size) {
    const float* x     = (const float*)d_in[0];   // [4, N]
    const float* w     = (const float*)d_in[1];   // [3]
    const float* v     = (const float*)d_in[2];   // [3]
    const float* theta = (const float*)d_in[3];   // scalar

    const int N   = in_sizes[0] / 4;
    const int n4  = N / 4;
    const int rem = N - n4 * 4;

    if (n4 > 0) {
        const int threads = 256;
        const int per_block = threads * 2;            // 2 float4 columns/thread
        const int blocks = (n4 + per_block - 1) / per_block;
        se3_fused_vec4x2<<<blocks, threads>>>((const float4*)x, (float4*)d_out,
                                              w, v, theta, n4);
    }
    if (rem > 0) {
        se3_tail<<<1, 128>>>(x, (float*)d_out, w, v, theta, N, n4 * 4);
    }
}

// round 10
// speedup vs baseline: 1.0019x; 1.0019x over previous
#include <cuda_runtime.h>

// Fused kernel: every thread rebuilds the 3x4 SE3 matrix from the 7 scalar
// inputs (uniform broadcast loads, ~100 ALU/MUFU ops — negligible vs HBM),
// then streams 2 float4 columns: y[r] = sum_c M[r][c] * x[c], y[3] = x[3].
__global__ __launch_bounds__(256)
void se3_fused_vec4x2(const float4* __restrict__ x, float4* __restrict__ y,
                      const float* __restrict__ w, const float* __restrict__ v,
                      const float* __restrict__ theta_p, int n4) {
    // ---- matrix build (uniform across all threads) ----
    const float wx = __ldg(w + 0), wy = __ldg(w + 1), wz = __ldg(w + 2);
    const float vx = __ldg(v + 0), vy = __ldg(v + 1), vz = __ldg(v + 2);
    const float theta = __ldg(theta_p);
    const float s = sinf(theta);
    const float c = cosf(theta);
    const float omc = 1.0f - c;     // 1 - cos
    const float tms = theta - s;    // theta - sin

    // K = skew(w); KK = K @ K
    const float K[9]  = { 0.0f, -wz,   wy,
                          wz,    0.0f, -wx,
                         -wy,    wx,   0.0f };
    float KK[9];
    #pragma unroll
    for (int r = 0; r < 3; r++)
        #pragma unroll
        for (int col = 0; col < 3; col++) {
            float acc = 0.0f;
            #pragma unroll
            for (int k = 0; k < 3; k++) acc += K[r * 3 + k] * K[k * 3 + col];
            KK[r * 3 + col] = acc;
        }

    float M[12];  // rows 0..2 of the 4x4; row 3 is [0,0,0,1]
    #pragma unroll
    for (int r = 0; r < 3; r++) {
        float Vr[3];
        #pragma unroll
        for (int col = 0; col < 3; col++) {
            const float I = (r == col) ? 1.0f : 0.0f;
            M[r * 4 + col] = I + s * K[r * 3 + col] + omc * KK[r * 3 + col];
            Vr[col]        = I * theta + omc * K[r * 3 + col] + tms * KK[r * 3 + col];
        }
        M[r * 4 + 3] = Vr[0] * vx + Vr[1] * vy + Vr[2] * vz;
    }
    const float m00 = M[0], m01 = M[1], m02 = M[2],  m03 = M[3];
    const float m10 = M[4], m11 = M[5], m12 = M[6],  m13 = M[7];
    const float m20 = M[8], m21 = M[9], m22 = M[10], m23 = M[11];

    // ---- streaming transform: 2 float4 columns per thread ----
    const size_t base = (size_t)(blockIdx.x * blockDim.x + threadIdx.x) * 2;
    const size_t stride = (size_t)n4;

    #pragma unroll
    for (int u = 0; u < 2; u++) {
        const size_t i = base + u;
        if (i >= stride) return;

        const float4 x0 = __ldcs(x + 0 * stride + i);
        const float4 x1 = __ldcs(x + 1 * stride + i);
        const float4 x2 = __ldcs(x + 2 * stride + i);
        const float4 x3 = __ldcs(x + 3 * stride + i);

        float4 y0, y1, y2;
        y0.x = m00 * x0.x + m01 * x1.x + m02 * x2.x + m03 * x3.x;
        y0.y = m00 * x0.y + m01 * x1.y + m02 * x2.y + m03 * x3.y;
        y0.z = m00 * x0.z + m01 * x1.z + m02 * x2.z + m03 * x3.z;
        y0.w = m00 * x0.w + m01 * x1.w + m02 * x2.w + m03 * x3.w;

        y1.x = m10 * x0.x + m11 * x1.x + m12 * x2.x + m13 * x3.x;
        y1.y = m10 * x0.y + m11 * x1.y + m12 * x2.y + m13 * x3.y;
        y1.z = m10 * x0.z + m11 * x1.z + m12 * x2.z + m13 * x3.z;
        y1.w = m10 * x0.w + m11 * x1.w + m12 * x2.w + m13 * x3.w;

        y2.x = m20 * x0.x + m21 * x1.x + m22 * x2.x + m23 * x3.x;
        y2.y = m20 * x0.y + m21 * x1.y + m22 * x2.y + m23 * x3.y;
        y2.z = m20 * x0.z + m21 * x1.z + m22 * x2.z + m23 * x3.z;
        y2.w = m20 * x0.w + m21 * x1.w + m22 * x2.w + m23 * x3.w;

        __stcs(y + 0 * stride + i, y0);
        __stcs(y + 1 * stride + i, y1);
        __stcs(y + 2 * stride + i, y2);
        __stcs(y + 3 * stride + i, x3);   // bottom row [0,0,0,1]
    }
}

// Scalar tail for N not divisible by 4 (defensive; N=16M is divisible).
__global__ void se3_tail(const float* __restrict__ x, float* __restrict__ y,
                         const float* __restrict__ w, const float* __restrict__ v,
                         const float* __restrict__ theta_p, int N, int start) {
    const int i = start + blockIdx.x * blockDim.x + threadIdx.x;
    if (i >= N) return;

    const float wx = w[0], wy = w[1], wz = w[2];
    const float theta = theta_p[0];
    const float s = sinf(theta), c = cosf(theta);
    const float omc = 1.0f - c, tms = theta - s;
    const float K[9]  = { 0.0f, -wz, wy,  wz, 0.0f, -wx,  -wy, wx, 0.0f };
    float KK[9];
    for (int r = 0; r < 3; r++)
        for (int col = 0; col < 3; col++) {
            float acc = 0.0f;
            for (int k = 0; k < 3; k++) acc += K[r * 3 + k] * K[k * 3 + col];
            KK[r * 3 + col] = acc;
        }
    float M[12];
    for (int r = 0; r < 3; r++) {
        float Vr[3];
        for (int col = 0; col < 3; col++) {
            const float I = (r == col) ? 1.0f : 0.0f;
            M[r * 4 + col] = I + s * K[r * 3 + col] + omc * KK[r * 3 + col];
            Vr[col]        = I * theta + omc * K[r * 3 + col] + tms * KK[r * 3 + col];
        }
        M[r * 4 + 3] = Vr[0] * v[0] + Vr[1] * v[1] + Vr[2] * v[2];
    }

    const float a = x[0 * (size_t)N + i];
    const float b = x[1 * (size_t)N + i];
    const float cc = x[2 * (size_t)N + i];
    const float d = x[3 * (size_t)N + i];
    y[0 * (size_t)N + i] = M[0] * a + M[1] * b + M[2]  * cc + M[3]  * d;
    y[1 * (size_t)N + i] = M[4] * a + M[5] * b + M[6]  * cc + M[7]  * d;
    y[2 * (size_t)N + i] = M[8] * a + M[9] * b + M[10] * cc + M[11] * d;
    y[3 * (size_t)N + i] = d;
}

extern "C" void kernel_launch(void* const* d_in, const int* in_sizes, int n_in,
                              void* d_out, int out_size) {
    const float* x     = (const float*)d_in[0];   // [4, N]
    const float* w     = (const float*)d_in[1];   // [3]
    const float* v     = (const float*)d_in[2];   // [3]
    const float* theta = (const float*)d_in[3];   // scalar

    const int N   = in_sizes[0] / 4;
    const int n4  = N / 4;
    const int rem = N - n4 * 4;

    if (n4 > 0) {
        const int threads = 256;
        const int per_block = threads * 2;            // 2 float4 columns/thread
        const int blocks = (n4 + per_block - 1) / per_block;
        se3_fused_vec4x2<<<blocks, threads>>>((const float4*)x, (float4*)d_out,
                                              w, v, theta, n4);
    }
    if (rem > 0) {
        se3_tail<<<1, 128>>>(x, (float*)d_out, w, v, theta, N, n4 * 4);
    }
}

// round 13
// speedup vs baseline: 1.0052x; 1.0033x over previous
#include <cuda_runtime.h>

// Fused kernel: every thread rebuilds the 3x4 SE3 matrix from the 7 scalar
// inputs (uniform broadcast loads, ~100 ALU/MUFU ops — negligible vs HBM),
// then streams 2 float4 columns: y[r] = sum_c M[r][c] * x[c], y[3] = x[3].
__global__ __launch_bounds__(256)
void se3_fused_vec4x2(const float4* __restrict__ x, float4* __restrict__ y,
                      const float* __restrict__ w, const float* __restrict__ v,
                      const float* __restrict__ theta_p, int n4) {
    // ---- matrix build (uniform across all threads) ----
    const float wx = __ldg(w + 0), wy = __ldg(w + 1), wz = __ldg(w + 2);
    const float vx = __ldg(v + 0), vy = __ldg(v + 1), vz = __ldg(v + 2);
    const float theta = __ldg(theta_p);
    const float s = sinf(theta);
    const float c = cosf(theta);
    const float omc = 1.0f - c;     // 1 - cos
    const float tms = theta - s;    // theta - sin

    // K = skew(w); KK = K @ K
    const float K[9]  = { 0.0f, -wz,   wy,
                          wz,    0.0f, -wx,
                         -wy,    wx,   0.0f };
    float KK[9];
    #pragma unroll
    for (int r = 0; r < 3; r++)
        #pragma unroll
        for (int col = 0; col < 3; col++) {
            float acc = 0.0f;
            #pragma unroll
            for (int k = 0; k < 3; k++) acc += K[r * 3 + k] * K[k * 3 + col];
            KK[r * 3 + col] = acc;
        }

    float M[12];  // rows 0..2 of the 4x4; row 3 is [0,0,0,1]
    #pragma unroll
    for (int r = 0; r < 3; r++) {
        float Vr[3];
        #pragma unroll
        for (int col = 0; col < 3; col++) {
            const float I = (r == col) ? 1.0f : 0.0f;
            M[r * 4 + col] = I + s * K[r * 3 + col] + omc * KK[r * 3 + col];
            Vr[col]        = I * theta + omc * K[r * 3 + col] + tms * KK[r * 3 + col];
        }
        M[r * 4 + 3] = Vr[0] * vx + Vr[1] * vy + Vr[2] * vz;
    }
    const float m00 = M[0], m01 = M[1], m02 = M[2],  m03 = M[3];
    const float m10 = M[4], m11 = M[5], m12 = M[6],  m13 = M[7];
    const float m20 = M[8], m21 = M[9], m22 = M[10], m23 = M[11];

    // ---- streaming transform: 2 float4 columns per thread ----
    const size_t base = (size_t)(blockIdx.x * blockDim.x + threadIdx.x) * 2;
    const size_t stride = (size_t)n4;

    #pragma unroll
    for (int u = 0; u < 2; u++) {
        const size_t i = base + u;
        if (i >= stride) return;

        const float4 x0 = __ldcs(x + 0 * stride + i);
        const float4 x1 = __ldcs(x + 1 * stride + i);
        const float4 x2 = __ldcs(x + 2 * stride + i);
        const float4 x3 = __ldcs(x + 3 * stride + i);

        float4 y0, y1, y2;
        y0.x = m00 * x0.x + m01 * x1.x + m02 * x2.x + m03 * x3.x;
        y0.y = m00 * x0.y + m01 * x1.y + m02 * x2.y + m03 * x3.y;
        y0.z = m00 * x0.z + m01 * x1.z + m02 * x2.z + m03 * x3.z;
        y0.w = m00 * x0.w + m01 * x1.w + m02 * x2.w + m03 * x3.w;

        y1.x = m10 * x0.x + m11 * x1.x + m12 * x2.x + m13 * x3.x;
        y1.y = m10 * x0.y + m11 * x1.y + m12 * x2.y + m13 * x3.y;
        y1.z = m10 * x0.z + m11 * x1.z + m12 * x2.z + m13 * x3.z;
        y1.w = m10 * x0.w + m11 * x1.w + m12 * x2.w + m13 * x3.w;

        y2.x = m20 * x0.x + m21 * x1.x + m22 * x2.x + m23 * x3.x;
        y2.y = m20 * x0.y + m21 * x1.y + m22 * x2.y + m23 * x3.y;
        y2.z = m20 * x0.z + m21 * x1.z + m22 * x2.z + m23 * x3.z;
        y2.w = m20 * x0.w + m21 * x1.w + m22 * x2.w + m23 * x3.w;

        __stcs(y + 0 * stride + i, y0);
        __stcs(y + 1 * stride + i, y1);
        __stcs(y + 2 * stride + i, y2);
        __stcs(y + 3 * stride + i, x3);   // bottom row [0,0,0,1]
    }
}

// Scalar tail for N not divisible by 4 (defensive; N=16M is divisible).
__global__ void se3_tail(const float* __restrict__ x, float* __restrict__ y,
                         const float* __restrict__ w, const float* __restrict__ v,
                         const float* __restrict__ theta_p, int N, int start) {
    const int i = start + blockIdx.x * blockDim.x + threadIdx.x;
    if (i >= N) return;

    const float wx = w[0], wy = w[1], wz = w[2];
    const float theta = theta_p[0];
    const float s = sinf(theta), c = cosf(theta);
    const float omc = 1.0f - c, tms = theta - s;
    const float K[9]  = { 0.0f, -wz, wy,  wz, 0.0f, -wx,  -wy, wx, 0.0f };
    float KK[9];
    for (int r = 0; r < 3; r++)
        for (int col = 0; col < 3; col++) {
            float acc = 0.0f;
            for (int k = 0; k < 3; k++) acc += K[r * 3 + k] * K[k * 3 + col];
            KK[r * 3 + col] = acc;
        }
    float M[12];
    for (int r = 0; r < 3; r++) {
        float Vr[3];
        for (int col = 0; col < 3; col++) {
            const float I = (r == col) ? 1.0f : 0.0f;
            M[r * 4 + col] = I + s * K[r * 3 + col] + omc * KK[r * 3 + col];
            Vr[col]        = I * theta + omc * K[r * 3 + col] + tms * KK[r * 3 + col];
        }
        M[r * 4 + 3] = Vr[0] * v[0] + Vr[1] * v[1] + Vr[2] * v[2];
    }

    const float a = x[0 * (size_t)N + i];
    const float b = x[1 * (size_t)N + i];
    const float cc = x[2 * (size_t)N + i];
    const float d = x[3 * (size_t)N + i];
    y[0 * (size_t)N + i] = M[0] * a + M[1] * b + M[2]  * cc + M[3]  * d;
    y[1 * (size_t)N + i] = M[4] * a + M[5] * b + M[6]  * cc + M[7]  * d;
    y[2 * (size_t)N + i] = M[8] * a + M[9] * b + M[10] * cc + M[11] * d;
    y[3 * (size_t)N + i] = d;
}

extern "C" void kernel_launch(void* const* d_in, const int* in_sizes, int n_in,
                              void* d_out, int out_size) {
    const float* x     = (const float*)d_in[0];   // [4, N]
    const float* w     = (const float*)d_in[1];   // [3]
    const float* v     = (const float*)d_in[2];   // [3]
    const float* theta = (const float*)d_in[3];   // scalar

    const int N   = in_sizes[0] / 4;
    const int n4  = N / 4;
    const int rem = N - n4 * 4;

    if (n4 > 0) {
        const int threads = 256;
        const int per_block = threads * 2;            // 2 float4 columns/thread
        const int blocks = (n4 + per_block - 1) / per_block;
        se3_fused_vec4x2<<<blocks, threads>>>((const float4*)x, (float4*)d_out,
                                              w, v, theta, n4);
    }
    if (rem > 0) {
        se3_tail<<<1, 128>>>(x, (float*)d_out, w, v, theta, N, n4 * 4);
    }
}

// round 14
// speedup vs baseline: 1.2554x; 1.2489x over previous
#include <cuda_runtime.h>

// Single fused kernel. Thread 0 of each block builds the 3x4 SE3 matrix
// (exact fp32 reference math) into shared memory; all threads broadcast-read
// it, then stream 2 block-strided float4 columns:
//   y[r][i] = sum_c M[r][c] * x[c][i],  y[3][i] = x[3][i].
__global__ __launch_bounds__(256)
void se3_fused_bcast(const float4* __restrict__ x, float4* __restrict__ y,
                     const float* __restrict__ w, const float* __restrict__ v,
                     const float* __restrict__ theta_p, int n4) {
    __shared__ float sM[12];

    if (threadIdx.x == 0) {
        const float wx = w[0], wy = w[1], wz = w[2];
        const float theta = theta_p[0];
        const float s = sinf(theta);
        const float c = cosf(theta);
        const float omc = 1.0f - c;     // 1 - cos(theta)
        const float tms = theta - s;    // theta - sin(theta)

        // K = skew(w); KK = K @ K
        const float K[9] = { 0.0f, -wz,   wy,
                             wz,    0.0f, -wx,
                            -wy,    wx,   0.0f };
        float KK[9];
        #pragma unroll
        for (int r = 0; r < 3; r++)
            #pragma unroll
            for (int col = 0; col < 3; col++) {
                float acc = 0.0f;
                #pragma unroll
                for (int k = 0; k < 3; k++) acc += K[r * 3 + k] * K[k * 3 + col];
                KK[r * 3 + col] = acc;
            }

        const float vx = v[0], vy = v[1], vz = v[2];
        #pragma unroll
        for (int r = 0; r < 3; r++) {
            float Vr[3];
            #pragma unroll
            for (int col = 0; col < 3; col++) {
                const float I = (r == col) ? 1.0f : 0.0f;
                sM[r * 4 + col] = I + s * K[r * 3 + col] + omc * KK[r * 3 + col];
                Vr[col]         = I * theta + omc * K[r * 3 + col] + tms * KK[r * 3 + col];
            }
            sM[r * 4 + 3] = Vr[0] * vx + Vr[1] * vy + Vr[2] * vz;
        }
    }
    __syncthreads();

    const float m00 = sM[0], m01 = sM[1], m02 = sM[2],  m03 = sM[3];
    const float m10 = sM[4], m11 = sM[5], m12 = sM[6],  m13 = sM[7];
    const float m20 = sM[8], m21 = sM[9], m22 = sM[10], m23 = sM[11];

    // Block-strided: block b owns columns [b*512, b*512+512); thread t does
    // columns b*512+t and b*512+t+256. Every warp access is contiguous 512B.
    const size_t stride = (size_t)n4;
    const size_t base = (size_t)blockIdx.x * 512 + threadIdx.x;

    #pragma unroll
    for (int u = 0; u < 2; u++) {
        const size_t i = base + (size_t)u * 256;
        if (i >= stride) break;

        const float4 x0 = __ldcs(x + 0 * stride + i);
        const float4 x1 = __ldcs(x + 1 * stride + i);
        const float4 x2 = __ldcs(x + 2 * stride + i);
        const float4 x3 = __ldcs(x + 3 * stride + i);

        float4 y0, y1, y2;
        y0.x = m00 * x0.x + m01 * x1.x + m02 * x2.x + m03 * x3.x;
        y0.y = m00 * x0.y + m01 * x1.y + m02 * x2.y + m03 * x3.y;
        y0.z = m00 * x0.z + m01 * x1.z + m02 * x2.z + m03 * x3.z;
        y0.w = m00 * x0.w + m01 * x1.w + m02 * x2.w + m03 * x3.w;

        y1.x = m10 * x0.x + m11 * x1.x + m12 * x2.x + m13 * x3.x;
        y1.y = m10 * x0.y + m11 * x1.y + m12 * x2.y + m13 * x3.y;
        y1.z = m10 * x0.z + m11 * x1.z + m12 * x2.z + m13 * x3.z;
        y1.w = m10 * x0.w + m11 * x1.w + m12 * x2.w + m13 * x3.w;

        y2.x = m20 * x0.x + m21 * x1.x + m22 * x2.x + m23 * x3.x;
        y2.y = m20 * x0.y + m21 * x1.y + m22 * x2.y + m23 * x3.y;
        y2.z = m20 * x0.z + m21 * x1.z + m22 * x2.z + m23 * x3.z;
        y2.w = m20 * x0.w + m21 * x1.w + m22 * x2.w + m23 * x3.w;

        __stcs(y + 0 * stride + i, y0);
        __stcs(y + 1 * stride + i, y1);
        __stcs(y + 2 * stride + i, y2);
        __stcs(y + 3 * stride + i, x3);   // bottom row [0,0,0,1]
    }
}

// Scalar tail for N not divisible by 4 (defensive; N=16M is divisible).
__global__ void se3_tail(const float* __restrict__ x, float* __restrict__ y,
                         const float* __restrict__ w, const float* __restrict__ v,
                         const float* __restrict__ theta_p, int N, int start) {
    const int i = start + blockIdx.x * blockDim.x + threadIdx.x;
    if (i >= N) return;

    const float wx = w[0], wy = w[1], wz = w[2];
    const float theta = theta_p[0];
    const float s = sinf(theta), c = cosf(theta);
    const float omc = 1.0f - c, tms = theta - s;
    const float K[9] = { 0.0f, -wz, wy,  wz, 0.0f, -wx,  -wy, wx, 0.0f };
    float KK[9];
    for (int r = 0; r < 3; r++)
        for (int col = 0; col < 3; col++) {
            float acc = 0.0f;
            for (int k = 0; k < 3; k++) acc += K[r * 3 + k] * K[k * 3 + col];
            KK[r * 3 + col] = acc;
        }
    float M[12];
    for (int r = 0; r < 3; r++) {
        float Vr[3];
        for (int col = 0; col < 3; col++) {
            const float I = (r == col) ? 1.0f : 0.0f;
            M[r * 4 + col] = I + s * K[r * 3 + col] + omc * KK[r * 3 + col];
            Vr[col]        = I * theta + omc * K[r * 3 + col] + tms * KK[r * 3 + col];
        }
        M[r * 4 + 3] = Vr[0] * v[0] + Vr[1] * v[1] + Vr[2] * v[2];
    }

    const float a  = x[0 * (size_t)N + i];
    const float b  = x[1 * (size_t)N + i];
    const float cc = x[2 * (size_t)N + i];
    const float d  = x[3 * (size_t)N + i];
    y[0 * (size_t)N + i] = M[0] * a + M[1] * b + M[2]  * cc + M[3]  * d;
    y[1 * (size_t)N + i] = M[4] * a + M[5] * b + M[6]  * cc + M[7]  * d;
    y[2 * (size_t)N + i] = M[8] * a + M[9] * b + M[10] * cc + M[11] * d;
    y[3 * (size_t)N + i] = d;
}

extern "C" void kernel_launch(void* const* d_in, const int* in_sizes, int n_in,
                              void* d_out, int out_size) {
    const float* x     = (const float*)d_in[0];   // [4, N]
    const float* w     = (const float*)d_in[1];   // [3]
    const float* v     = (const float*)d_in[2];   // [3]
    const float* theta = (const float*)d_in[3];   // scalar

    const int N   = in_sizes[0] / 4;
    const int n4  = N / 4;
    const int rem = N - n4 * 4;

    if (n4 > 0) {
        const int threads = 256;
        const int per_block = threads * 2;            // 2 float4 columns/thread
        const int blocks = (n4 + per_block - 1) / per_block;
        se3_fused_bcast<<<blocks, threads>>>((const float4*)x, (float4*)d_out,
                                             w, v, theta, n4);
    }
    if (rem > 0) {
        se3_tail<<<1, 128>>>(x, (float*)d_out, w, v, theta, N, n4 * 4);
    }
}